// round 15
// baseline (speedup 1.0000x reference)
#include <cuda_runtime.h>

typedef unsigned long long ull;

#define Bn 256
#define Tn 512
#define Dn 64
#define Hn 128
#define BTn (Bn*Tn)

// Scratch (allocation-free rule: __device__ globals)
__device__ float g_Gh[(size_t)BTn*Hn];
__device__ float g_Pz[(size_t)BTn*Hn];
__device__ float g_Pr[(size_t)BTn*Hn];
__device__ float g_Ph[(size_t)BTn*Hn];

__device__ __forceinline__ ull pk2(float x, float y){
    ull r; asm("mov.b64 %0,{%1,%2};" : "=l"(r) : "f"(x), "f"(y)); return r;
}
__device__ __forceinline__ ull fma2(ull a, ull b, ull c){
    ull d; asm("fma.rn.f32x2 %0,%1,%2,%3;" : "=l"(d) : "l"(a), "l"(b), "l"(c)); return d;
}
__device__ __forceinline__ float2 up2(ull v){
    float2 f; asm("mov.b64 {%0,%1},%2;" : "=f"(f.x), "=f"(f.y) : "l"(v)); return f;
}
__device__ __forceinline__ float hadd2(ull v){
    float2 f = up2(v); return f.x + f.y;
}

// ---------------------------------------------------------------------------
// Phase 1: recurrence-free precompute.
// x'/m stored in smem PRE-DUPLICATED as (v,v) ull pairs -> no per-fma2 MOVs.
// ---------------------------------------------------------------------------
__global__ void __launch_bounds__(256,2) phase1_kernel(
    const float* __restrict__ values, const float* __restrict__ masks,
    const float* __restrict__ deltas, const float* __restrict__ emean,
    const float* __restrict__ xlocf,  const float* __restrict__ w_gamma_x,
    const float* __restrict__ w_gamma_h, const float* __restrict__ w_rx,
    const float* __restrict__ w_rm,   const float* __restrict__ w_zx,
    const float* __restrict__ w_zm,   const float* __restrict__ w_hx,
    const float* __restrict__ w_hm,   const float* __restrict__ b_gamma_x,
    const float* __restrict__ b_gamma_h, const float* __restrict__ b_r,
    const float* __restrict__ b_z,    const float* __restrict__ b_h)
{
    __shared__ ull  sxu[2048];   // (x',x') pairs [32][64]
    __shared__ ull  smu[2048];   // (m,m) pairs
    __shared__ float sdd[2048];  // dlt scalar

    const int tid = threadIdx.x;
    const int rowbase = blockIdx.x * 32;

    for (int idx = tid; idx < 2048; idx += 256) {
        int k = idx & 63;
        int g = rowbase * 64 + idx;
        float x  = values[g];
        float m  = masks[g];
        float d  = deltas[g];
        float xl = xlocf[g];
        float gx = __expf(-fmaxf(fmaf(w_gamma_x[k], d, b_gamma_x[k]), 0.f));
        float xp = m * x + (1.f - m) * (gx * xl + (1.f - gx) * emean[k]);
        sxu[idx] = pk2(xp, xp);
        smu[idx] = pk2(m, m);
        sdd[idx] = d;
    }
    __syncthreads();

    const int jp = tid & 63;       // column pair: cols {2jp, 2jp+1}
    const int rb = (tid >> 6) * 8; // 8 rows per thread

    ull aG[8], aZ[8], aR[8], aH[8];
    #pragma unroll
    for (int r = 0; r < 8; r++) { aG[r]=0ull; aZ[r]=0ull; aR[r]=0ull; aH[r]=0ull; }

    const ull* Wg  = (const ull*)w_gamma_h;
    const ull* Wzx = (const ull*)w_zx;  const ull* Wzm = (const ull*)w_zm;
    const ull* Wrx = (const ull*)w_rx;  const ull* Wrm = (const ull*)w_rm;
    const ull* Whx = (const ull*)w_hx;  const ull* Whm = (const ull*)w_hm;

    #pragma unroll 2
    for (int k = 0; k < 64; k++) {
        int wo = k * 64 + jp;
        ull wg  = Wg[wo];
        ull wzx = Wzx[wo], wzm = Wzm[wo];
        ull wrx = Wrx[wo], wrm = Wrm[wo];
        ull whx = Whx[wo], whm = Whm[wo];
        #pragma unroll
        for (int r = 0; r < 8; r++) {
            int o = (rb + r) * 64 + k;
            ull x2 = sxu[o];
            ull m2 = smu[o];
            float dv = sdd[o];
            ull d2 = pk2(dv, dv);
            aG[r] = fma2(d2, wg,  aG[r]);
            aZ[r] = fma2(x2, wzx, aZ[r]);
            aZ[r] = fma2(m2, wzm, aZ[r]);
            aR[r] = fma2(x2, wrx, aR[r]);
            aR[r] = fma2(m2, wrm, aR[r]);
            aH[r] = fma2(x2, whx, aH[r]);
            aH[r] = fma2(m2, whm, aH[r]);
        }
    }

    float2 bgh = ((const float2*)b_gamma_h)[jp];
    float2 bz  = ((const float2*)b_z)[jp];
    float2 br  = ((const float2*)b_r)[jp];
    float2 bh  = ((const float2*)b_h)[jp];
    float2* Gho = (float2*)g_Gh;
    float2* Pzo = (float2*)g_Pz;
    float2* Pro = (float2*)g_Pr;
    float2* Pho = (float2*)g_Ph;

    #pragma unroll
    for (int r = 0; r < 8; r++) {
        int row = rowbase + rb + r;
        int o = row * 64 + jp;
        float2 v = up2(aG[r]);
        float2 w;
        w.x = __expf(-fmaxf(v.x + bgh.x, 0.f));
        w.y = __expf(-fmaxf(v.y + bgh.y, 0.f));
        Gho[o] = w;
        v = up2(aZ[r]); v.x += bz.x; v.y += bz.y; Pzo[o] = v;
        v = up2(aR[r]); v.x += br.x; v.y += br.y; Pro[o] = v;
        v = up2(aH[r]); v.x += bh.x; v.y += bh.y; Pho[o] = v;
    }
}

// ---------------------------------------------------------------------------
// Phase 2: recurrence with register-resident weights.
// 128 CTAs x 2 batch rows, 256 threads.
// Thread map: warp w, lane l -> j = w*16 + (l>>1), half = l&1.
// Cross-half partial exchange via shfl.xor(1) (NO barrier).
// hg / r*h read as ulonglong2 (LDS.128, no repack MOVs); k>=64 region offset
// +8 floats to dodge the broadcast bank conflict. 2 barriers per step.
// ---------------------------------------------------------------------------
__global__ void __launch_bounds__(256,1) phase2_kernel(
    const float* __restrict__ w_zh, const float* __restrict__ w_rh,
    const float* __restrict__ w_hh, float* __restrict__ out, int lastoff)
{
    __shared__ float shg0[136], shg1[136];   // hg rows 0/1; slot(k)=k+(k>=64?8:0)
    __shared__ float srh0[136], srh1[136];   // r*hg rows 0/1

    const int tid  = threadIdx.x;
    const int lane = tid & 31;
    const int warp = tid >> 5;
    const int j    = warp * 16 + (lane >> 1);  // output column
    const int half = lane & 1;                 // k-half: [0,64) or [64,128)
    const int kbase = half * 64;
    const int jslot = j + (j >= 64 ? 8 : 0);   // padded slot for writes

    // Register-resident weight half-columns, k-pair packed.
    ull wz[32], wr[32], wh[32];
    #pragma unroll
    for (int kp = 0; kp < 32; kp++) {
        int k0 = kbase + 2 * kp;
        wz[kp] = pk2(w_zh[k0 * Hn + j], w_zh[(k0 + 1) * Hn + j]);
        wr[kp] = pk2(w_rh[k0 * Hn + j], w_rh[(k0 + 1) * Hn + j]);
        wh[kp] = pk2(w_hh[k0 * Hn + j], w_hh[(k0 + 1) * Hn + j]);
    }

    const int b0 = blockIdx.x * 2;
    const int stride_b = Tn * Hn;

    const float* pG0 = g_Gh + b0 * stride_b + j;  const float* pG1 = pG0 + stride_b;
    const float* pZ0 = g_Pz + b0 * stride_b + j;  const float* pZ1 = pZ0 + stride_b;
    const float* pR0 = g_Pr + b0 * stride_b + j;  const float* pR1 = pR0 + stride_b;
    const float* pH0 = g_Ph + b0 * stride_b + j;  const float* pH1 = pH0 + stride_b;
    float* o0 = out + b0 * stride_b + j;
    float* o1 = o0 + stride_b;

    float h0 = 0.f, h1 = 0.f;

    float nG0 = pG0[0], nG1 = pG1[0];
    float nZ0 = pZ0[0], nZ1 = pZ1[0];
    float nR0 = pR0[0], nR1 = pR1[0];
    float nH0 = pH0[0], nH1 = pH1[0];

    // Own-half ull2 views (16 entries each): entry q covers k = kbase+4q..+3
    const ulonglong2* hg04 = (const ulonglong2*)(shg0 + kbase + half * 8);
    const ulonglong2* hg14 = (const ulonglong2*)(shg1 + kbase + half * 8);
    const ulonglong2* rh04 = (const ulonglong2*)(srh0 + kbase + half * 8);
    const ulonglong2* rh14 = (const ulonglong2*)(srh1 + kbase + half * 8);

    for (int t = 0; t < Tn; t++) {
        float G0 = nG0, G1 = nG1, Z0 = nZ0, Z1 = nZ1;
        float R0 = nR0, R1 = nR1, Hp0 = nH0, Hp1 = nH1;
        int on = (t + 1 < Tn) ? (t + 1) * Hn : t * Hn;
        nG0 = pG0[on]; nG1 = pG1[on];
        nZ0 = pZ0[on]; nZ1 = pZ1[on];
        nR0 = pR0[on]; nR1 = pR1[on];
        nH0 = pH0[on]; nH1 = pH1[on];

        float hg0 = G0 * h0, hg1 = G1 * h1;
        if (half == 0) { shg0[jslot] = hg0; shg1[jslot] = hg1; }
        __syncthreads();                                   // S1: hg published

        ull az0 = 0ull, az1 = 0ull, ar0 = 0ull, ar1 = 0ull;
        #pragma unroll
        for (int q = 0; q < 16; q++) {
            ulonglong2 a0 = hg04[q];
            ulonglong2 a1 = hg14[q];
            az0 = fma2(a0.x, wz[2*q],   az0);
            az0 = fma2(a0.y, wz[2*q+1], az0);
            az1 = fma2(a1.x, wz[2*q],   az1);
            az1 = fma2(a1.y, wz[2*q+1], az1);
            ar0 = fma2(a0.x, wr[2*q],   ar0);
            ar0 = fma2(a0.y, wr[2*q+1], ar0);
            ar1 = fma2(a1.x, wr[2*q],   ar1);
            ar1 = fma2(a1.y, wr[2*q+1], ar1);
        }
        float paz0 = hadd2(az0), paz1 = hadd2(az1);
        float par0 = hadd2(ar0), par1 = hadd2(ar1);
        // cross-half exchange: partner lane = lane ^ 1 (same j, other half)
        float sz0 = Z0 + paz0 + __shfl_xor_sync(0xffffffffu, paz0, 1);
        float sz1 = Z1 + paz1 + __shfl_xor_sync(0xffffffffu, paz1, 1);
        float sr0 = R0 + par0 + __shfl_xor_sync(0xffffffffu, par0, 1);
        float sr1 = R1 + par1 + __shfl_xor_sync(0xffffffffu, par1, 1);
        float z0 = 1.f / (1.f + __expf(-sz0));
        float z1 = 1.f / (1.f + __expf(-sz1));
        float r0 = 1.f / (1.f + __expf(-sr0));
        float r1 = 1.f / (1.f + __expf(-sr1));

        if (half == 0) { srh0[jslot] = r0 * hg0; srh1[jslot] = r1 * hg1; }
        __syncthreads();                                   // S2: r*hg published

        ull ah0 = 0ull, ah1 = 0ull;
        #pragma unroll
        for (int q = 0; q < 16; q++) {
            ulonglong2 a0 = rh04[q];
            ulonglong2 a1 = rh14[q];
            ah0 = fma2(a0.x, wh[2*q],   ah0);
            ah0 = fma2(a0.y, wh[2*q+1], ah0);
            ah1 = fma2(a1.x, wh[2*q],   ah1);
            ah1 = fma2(a1.y, wh[2*q+1], ah1);
        }
        float pah0 = hadd2(ah0), pah1 = hadd2(ah1);
        float sa0 = Hp0 + pah0 + __shfl_xor_sync(0xffffffffu, pah0, 1);
        float sa1 = Hp1 + pah1 + __shfl_xor_sync(0xffffffffu, pah1, 1);
        float e0 = __expf(2.f * sa0), e1 = __expf(2.f * sa1);
        float th0 = 1.f - 2.f / (e0 + 1.f);
        float th1 = 1.f - 2.f / (e1 + 1.f);

        h0 = (1.f - z0) * hg0 + z0 * th0;
        h1 = (1.f - z1) * hg1 + z1 * th1;

        if (half == 0) {
            o0[t * Hn] = h0;
            o1[t * Hn] = h1;
        }
    }
    if (half == 0) {
        out[lastoff + (b0 + 0) * Hn + j] = h0;
        out[lastoff + (b0 + 1) * Hn + j] = h1;
    }
}

extern "C" void kernel_launch(void* const* d_in, const int* in_sizes, int n_in,
                              void* d_out, int out_size)
{
    const float* values = (const float*)d_in[0];
    const float* masks  = (const float*)d_in[1];
    const float* deltas = (const float*)d_in[2];
    const float* emean  = (const float*)d_in[3];
    const float* xlocf  = (const float*)d_in[4];
    const float* w_gamma_x = (const float*)d_in[5];
    const float* w_gamma_h = (const float*)d_in[6];
    const float* w_rx = (const float*)d_in[7];
    const float* w_rh = (const float*)d_in[8];
    const float* w_rm = (const float*)d_in[9];
    const float* w_zx = (const float*)d_in[10];
    const float* w_zh = (const float*)d_in[11];
    const float* w_zm = (const float*)d_in[12];
    const float* w_hx = (const float*)d_in[13];
    const float* w_hh = (const float*)d_in[14];
    const float* w_hm = (const float*)d_in[15];
    const float* b_gamma_x = (const float*)d_in[16];
    const float* b_gamma_h = (const float*)d_in[17];
    const float* b_r = (const float*)d_in[18];
    const float* b_z = (const float*)d_in[19];
    const float* b_h = (const float*)d_in[20];

    phase1_kernel<<<BTn/32, 256>>>(values, masks, deltas, emean, xlocf,
                                   w_gamma_x, w_gamma_h, w_rx, w_rm, w_zx, w_zm,
                                   w_hx, w_hm, b_gamma_x, b_gamma_h, b_r, b_z, b_h);

    int lastoff = out_size - Bn * Hn;   // h_last tail offset, derived not hard-coded
    phase2_kernel<<<Bn/2, 256>>>(w_zh, w_rh, w_hh, (float*)d_out, lastoff);
}

// round 16
// speedup vs baseline: 1.2800x; 1.2800x over previous
#include <cuda_runtime.h>

typedef unsigned long long ull;

#define Bn 256
#define Tn 512
#define Dn 64
#define Hn 128
#define BTn (Bn*Tn)

// Scratch (allocation-free rule: __device__ globals)
__device__ float g_Gh[(size_t)BTn*Hn];
__device__ float g_Pz[(size_t)BTn*Hn];
__device__ float g_Pr[(size_t)BTn*Hn];
__device__ float g_Ph[(size_t)BTn*Hn];

__device__ __forceinline__ ull pk2(float x, float y){
    ull r; asm("mov.b64 %0,{%1,%2};" : "=l"(r) : "f"(x), "f"(y)); return r;
}
__device__ __forceinline__ ull fma2(ull a, ull b, ull c){
    ull d; asm("fma.rn.f32x2 %0,%1,%2,%3;" : "=l"(d) : "l"(a), "l"(b), "l"(c)); return d;
}
__device__ __forceinline__ float2 up2(ull v){
    float2 f; asm("mov.b64 {%0,%1},%2;" : "=f"(f.x), "=f"(f.y) : "l"(v)); return f;
}
__device__ __forceinline__ float hadd2(ull v){
    float2 f = up2(v); return f.x + f.y;
}
__device__ __forceinline__ float tanh_approx(float x){
    float y; asm("tanh.approx.f32 %0, %1;" : "=f"(y) : "f"(x)); return y;
}

// ---------------------------------------------------------------------------
// Phase 1: recurrence-free precompute — EXACT R5 version (measured 434 us;
// the R6 ull-smem variant regressed to ~598 us, reverted).
// ---------------------------------------------------------------------------
__global__ void __launch_bounds__(256,2) phase1_kernel(
    const float* __restrict__ values, const float* __restrict__ masks,
    const float* __restrict__ deltas, const float* __restrict__ emean,
    const float* __restrict__ xlocf,  const float* __restrict__ w_gamma_x,
    const float* __restrict__ w_gamma_h, const float* __restrict__ w_rx,
    const float* __restrict__ w_rm,   const float* __restrict__ w_zx,
    const float* __restrict__ w_zm,   const float* __restrict__ w_hx,
    const float* __restrict__ w_hm,   const float* __restrict__ b_gamma_x,
    const float* __restrict__ b_gamma_h, const float* __restrict__ b_r,
    const float* __restrict__ b_z,    const float* __restrict__ b_h)
{
    __shared__ float sx[2048];   // x' tile [32][64]
    __shared__ float smm[2048];  // m  tile
    __shared__ float sdd[2048];  // dlt tile

    const int tid = threadIdx.x;
    const int rowbase = blockIdx.x * 32;

    for (int idx = tid; idx < 2048; idx += 256) {
        int k = idx & 63;
        int g = rowbase * 64 + idx;
        float x  = values[g];
        float m  = masks[g];
        float d  = deltas[g];
        float xl = xlocf[g];
        float gx = __expf(-fmaxf(fmaf(w_gamma_x[k], d, b_gamma_x[k]), 0.f));
        sx[idx]  = m * x + (1.f - m) * (gx * xl + (1.f - gx) * emean[k]);
        smm[idx] = m;
        sdd[idx] = d;
    }
    __syncthreads();

    const int jp = tid & 63;       // column pair: cols {2jp, 2jp+1}
    const int rb = (tid >> 6) * 8; // 8 rows per thread

    ull aG[8], aZ[8], aR[8], aH[8];
    #pragma unroll
    for (int r = 0; r < 8; r++) { aG[r]=0ull; aZ[r]=0ull; aR[r]=0ull; aH[r]=0ull; }

    const ull* Wg  = (const ull*)w_gamma_h;
    const ull* Wzx = (const ull*)w_zx;  const ull* Wzm = (const ull*)w_zm;
    const ull* Wrx = (const ull*)w_rx;  const ull* Wrm = (const ull*)w_rm;
    const ull* Whx = (const ull*)w_hx;  const ull* Whm = (const ull*)w_hm;

    #pragma unroll 2
    for (int k = 0; k < 64; k++) {
        int wo = k * 64 + jp;
        ull wg  = Wg[wo];
        ull wzx = Wzx[wo], wzm = Wzm[wo];
        ull wrx = Wrx[wo], wrm = Wrm[wo];
        ull whx = Whx[wo], whm = Whm[wo];
        #pragma unroll
        for (int r = 0; r < 8; r++) {
            int o = (rb + r) * 64 + k;
            float xv = sx[o], mv = smm[o], dv = sdd[o];
            ull x2 = pk2(xv, xv);
            ull m2 = pk2(mv, mv);
            ull d2 = pk2(dv, dv);
            aG[r] = fma2(d2, wg,  aG[r]);
            aZ[r] = fma2(x2, wzx, aZ[r]);
            aZ[r] = fma2(m2, wzm, aZ[r]);
            aR[r] = fma2(x2, wrx, aR[r]);
            aR[r] = fma2(m2, wrm, aR[r]);
            aH[r] = fma2(x2, whx, aH[r]);
            aH[r] = fma2(m2, whm, aH[r]);
        }
    }

    float2 bgh = ((const float2*)b_gamma_h)[jp];
    float2 bz  = ((const float2*)b_z)[jp];
    float2 br  = ((const float2*)b_r)[jp];
    float2 bh  = ((const float2*)b_h)[jp];
    float2* Gho = (float2*)g_Gh;
    float2* Pzo = (float2*)g_Pz;
    float2* Pro = (float2*)g_Pr;
    float2* Pho = (float2*)g_Ph;

    #pragma unroll
    for (int r = 0; r < 8; r++) {
        int row = rowbase + rb + r;
        int o = row * 64 + jp;
        float2 v = up2(aG[r]);
        float2 w;
        w.x = __expf(-fmaxf(v.x + bgh.x, 0.f));
        w.y = __expf(-fmaxf(v.y + bgh.y, 0.f));
        Gho[o] = w;
        v = up2(aZ[r]); v.x += bz.x; v.y += bz.y; Pzo[o] = v;
        v = up2(aR[r]); v.x += br.x; v.y += br.y; Pro[o] = v;
        v = up2(aH[r]); v.x += bh.x; v.y += bh.y; Pho[o] = v;
    }
}

// ---------------------------------------------------------------------------
// Phase 2: recurrence with register-resident weights (R15 structure, best
// measured 583.8 us) + critical-path latency cuts: tanh.approx MUFU and
// __fdividef sigmoid (measured bottleneck is serial latency, not issue count).
// ---------------------------------------------------------------------------
__global__ void __launch_bounds__(256,1) phase2_kernel(
    const float* __restrict__ w_zh, const float* __restrict__ w_rh,
    const float* __restrict__ w_hh, float* __restrict__ out, int lastoff)
{
    __shared__ float shg0[136], shg1[136];   // hg rows 0/1; slot(k)=k+(k>=64?8:0)
    __shared__ float srh0[136], srh1[136];   // r*hg rows 0/1

    const int tid  = threadIdx.x;
    const int lane = tid & 31;
    const int warp = tid >> 5;
    const int j    = warp * 16 + (lane >> 1);  // output column
    const int half = lane & 1;                 // k-half: [0,64) or [64,128)
    const int kbase = half * 64;
    const int jslot = j + (j >= 64 ? 8 : 0);   // padded slot for writes

    // Register-resident weight half-columns, k-pair packed.
    ull wz[32], wr[32], wh[32];
    #pragma unroll
    for (int kp = 0; kp < 32; kp++) {
        int k0 = kbase + 2 * kp;
        wz[kp] = pk2(w_zh[k0 * Hn + j], w_zh[(k0 + 1) * Hn + j]);
        wr[kp] = pk2(w_rh[k0 * Hn + j], w_rh[(k0 + 1) * Hn + j]);
        wh[kp] = pk2(w_hh[k0 * Hn + j], w_hh[(k0 + 1) * Hn + j]);
    }

    const int b0 = blockIdx.x * 2;
    const int stride_b = Tn * Hn;

    const float* pG0 = g_Gh + b0 * stride_b + j;  const float* pG1 = pG0 + stride_b;
    const float* pZ0 = g_Pz + b0 * stride_b + j;  const float* pZ1 = pZ0 + stride_b;
    const float* pR0 = g_Pr + b0 * stride_b + j;  const float* pR1 = pR0 + stride_b;
    const float* pH0 = g_Ph + b0 * stride_b + j;  const float* pH1 = pH0 + stride_b;
    float* o0 = out + b0 * stride_b + j;
    float* o1 = o0 + stride_b;

    float h0 = 0.f, h1 = 0.f;

    float nG0 = pG0[0], nG1 = pG1[0];
    float nZ0 = pZ0[0], nZ1 = pZ1[0];
    float nR0 = pR0[0], nR1 = pR1[0];
    float nH0 = pH0[0], nH1 = pH1[0];

    // Own-half ull2 views (16 entries each): entry q covers k = kbase+4q..+3
    const ulonglong2* hg04 = (const ulonglong2*)(shg0 + kbase + half * 8);
    const ulonglong2* hg14 = (const ulonglong2*)(shg1 + kbase + half * 8);
    const ulonglong2* rh04 = (const ulonglong2*)(srh0 + kbase + half * 8);
    const ulonglong2* rh14 = (const ulonglong2*)(srh1 + kbase + half * 8);

    for (int t = 0; t < Tn; t++) {
        float G0 = nG0, G1 = nG1, Z0 = nZ0, Z1 = nZ1;
        float R0 = nR0, R1 = nR1, Hp0 = nH0, Hp1 = nH1;
        int on = (t + 1 < Tn) ? (t + 1) * Hn : t * Hn;
        nG0 = pG0[on]; nG1 = pG1[on];
        nZ0 = pZ0[on]; nZ1 = pZ1[on];
        nR0 = pR0[on]; nR1 = pR1[on];
        nH0 = pH0[on]; nH1 = pH1[on];

        float hg0 = G0 * h0, hg1 = G1 * h1;
        if (half == 0) { shg0[jslot] = hg0; shg1[jslot] = hg1; }
        __syncthreads();                                   // S1: hg published

        ull az0 = 0ull, az1 = 0ull, ar0 = 0ull, ar1 = 0ull;
        #pragma unroll
        for (int q = 0; q < 16; q++) {
            ulonglong2 a0 = hg04[q];
            ulonglong2 a1 = hg14[q];
            az0 = fma2(a0.x, wz[2*q],   az0);
            az0 = fma2(a0.y, wz[2*q+1], az0);
            az1 = fma2(a1.x, wz[2*q],   az1);
            az1 = fma2(a1.y, wz[2*q+1], az1);
            ar0 = fma2(a0.x, wr[2*q],   ar0);
            ar0 = fma2(a0.y, wr[2*q+1], ar0);
            ar1 = fma2(a1.x, wr[2*q],   ar1);
            ar1 = fma2(a1.y, wr[2*q+1], ar1);
        }
        float paz0 = hadd2(az0), paz1 = hadd2(az1);
        float par0 = hadd2(ar0), par1 = hadd2(ar1);
        // cross-half exchange: partner lane = lane ^ 1 (same j, other half)
        float sz0 = Z0 + paz0 + __shfl_xor_sync(0xffffffffu, paz0, 1);
        float sz1 = Z1 + paz1 + __shfl_xor_sync(0xffffffffu, paz1, 1);
        float sr0 = R0 + par0 + __shfl_xor_sync(0xffffffffu, par0, 1);
        float sr1 = R1 + par1 + __shfl_xor_sync(0xffffffffu, par1, 1);
        float z0 = __fdividef(1.f, 1.f + __expf(-sz0));
        float z1 = __fdividef(1.f, 1.f + __expf(-sz1));
        float r0 = __fdividef(1.f, 1.f + __expf(-sr0));
        float r1 = __fdividef(1.f, 1.f + __expf(-sr1));

        if (half == 0) { srh0[jslot] = r0 * hg0; srh1[jslot] = r1 * hg1; }
        __syncthreads();                                   // S2: r*hg published

        ull ah0 = 0ull, ah1 = 0ull;
        #pragma unroll
        for (int q = 0; q < 16; q++) {
            ulonglong2 a0 = rh04[q];
            ulonglong2 a1 = rh14[q];
            ah0 = fma2(a0.x, wh[2*q],   ah0);
            ah0 = fma2(a0.y, wh[2*q+1], ah0);
            ah1 = fma2(a1.x, wh[2*q],   ah1);
            ah1 = fma2(a1.y, wh[2*q+1], ah1);
        }
        float pah0 = hadd2(ah0), pah1 = hadd2(ah1);
        float sa0 = Hp0 + pah0 + __shfl_xor_sync(0xffffffffu, pah0, 1);
        float sa1 = Hp1 + pah1 + __shfl_xor_sync(0xffffffffu, pah1, 1);
        float th0 = tanh_approx(sa0);
        float th1 = tanh_approx(sa1);

        h0 = (1.f - z0) * hg0 + z0 * th0;
        h1 = (1.f - z1) * hg1 + z1 * th1;

        if (half == 0) {
            o0[t * Hn] = h0;
            o1[t * Hn] = h1;
        }
    }
    if (half == 0) {
        out[lastoff + (b0 + 0) * Hn + j] = h0;
        out[lastoff + (b0 + 1) * Hn + j] = h1;
    }
}

extern "C" void kernel_launch(void* const* d_in, const int* in_sizes, int n_in,
                              void* d_out, int out_size)
{
    const float* values = (const float*)d_in[0];
    const float* masks  = (const float*)d_in[1];
    const float* deltas = (const float*)d_in[2];
    const float* emean  = (const float*)d_in[3];
    const float* xlocf  = (const float*)d_in[4];
    const float* w_gamma_x = (const float*)d_in[5];
    const float* w_gamma_h = (const float*)d_in[6];
    const float* w_rx = (const float*)d_in[7];
    const float* w_rh = (const float*)d_in[8];
    const float* w_rm = (const float*)d_in[9];
    const float* w_zx = (const float*)d_in[10];
    const float* w_zh = (const float*)d_in[11];
    const float* w_zm = (const float*)d_in[12];
    const float* w_hx = (const float*)d_in[13];
    const float* w_hh = (const float*)d_in[14];
    const float* w_hm = (const float*)d_in[15];
    const float* b_gamma_x = (const float*)d_in[16];
    const float* b_gamma_h = (const float*)d_in[17];
    const float* b_r = (const float*)d_in[18];
    const float* b_z = (const float*)d_in[19];
    const float* b_h = (const float*)d_in[20];

    phase1_kernel<<<BTn/32, 256>>>(values, masks, deltas, emean, xlocf,
                                   w_gamma_x, w_gamma_h, w_rx, w_rm, w_zx, w_zm,
                                   w_hx, w_hm, b_gamma_x, b_gamma_h, b_r, b_z, b_h);

    int lastoff = out_size - Bn * Hn;   // h_last tail offset, derived not hard-coded
    phase2_kernel<<<Bn/2, 256>>>(w_zh, w_rh, w_hh, (float*)d_out, lastoff);
}